// round 13
// baseline (speedup 1.0000x reference)
#include <cuda_runtime.h>
#include <cuda_fp16.h>
#include <cstdint>

// Problem constants
#define NTOK    65536
#define DDIM    256
#define KCODES  1024
#define MLVL    4
#define THREADS 512
#define RS      260            // fp32 residual row stride (floats)
#define MARGIN  1.5e-3f
#define SB_SC   1024.0f        // codebook f16 pre-scale
#define M2D     (-2.0f / SB_SC)
// Mixed tiling: 432 big tiles (128 tok) + 160 small tiles (64 tok) = 592 = 4*148
#define NBIG    432
#define NSMALL  160
#define GRID    (NBIG + NSMALL)

// SMEM byte offsets (dynamic smem, total 228880)
#define OFF_RSH    0            // 133120: [128][260] fp32 residual
#define OFF_AFRAG  133120       // 65536:  A fragments [mt][ks16][lane32] uint4
#define OFF_BBUF   198656       // 24576:  3 x 8KB B slices (ring)
// Overlays inside BBUF (dead while ring unused; barrier-separated):
#define OFF_HTD    198656       // float4 topDist[seg][tok] (8192) (.w = satT)
#define OFF_HTI    206848       // int4   topIdx [seg][tok] (8192)
#define OFF_REDD   217088       // double redD[512]         (4096)
#define OFF_E2     223232       // 4096
#define OFF_R2     227328       // 512
#define OFF_BEST   227840       // 512
#define OFF_CTOK   228352       // 512
#define OFF_CCNT   228864       // 16
#define SMEM_TOTAL 228880

__device__ float  g_e2[MLVL * KCODES];
__device__ double g_commitPartial[GRID];
// B fragments (f16, x1024): [lvl][slice(64)][512 x uint4] (8KB slices)
__device__ uint4  g_cbfrag[MLVL * 64 * 512];

static __device__ __forceinline__ uint32_t pkhf(float a, float b) {
    __half2 h = __floats2half2_rn(a, b);   // x=a (low), y=b (high)
    return *reinterpret_cast<uint32_t*>(&h);
}
// f16-accumulator HMMA: D,C are 2 regs of f16x2
static __device__ __forceinline__ void mma16816h(uint32_t* c, const uint4& A,
                                                 uint32_t b0, uint32_t b1) {
    asm volatile(
        "mma.sync.aligned.m16n8k16.row.col.f16.f16.f16.f16 "
        "{%0,%1}, {%2,%3,%4,%5}, {%6,%7}, {%0,%1};"
        : "+r"(c[0]), "+r"(c[1])
        : "r"(A.x), "r"(A.y), "r"(A.z), "r"(A.w), "r"(b0), "r"(b1));
}
static __device__ __forceinline__ void cpasync16(void* dst, const void* src) {
    uint32_t d = (uint32_t)__cvta_generic_to_shared(dst);
    asm volatile("cp.async.cg.shared.global [%0], [%1], 16;" :: "r"(d), "l"(src));
}
#define CP_COMMIT() asm volatile("cp.async.commit_group;")
#define CP_WAIT(n)  asm volatile("cp.async.wait_group %0;" :: "n"(n))

// ---------------------------------------------------------------------------
// Merged prep: f16(x1024) codebook fragment pack + per-warp e2 row (fp64).
// ---------------------------------------------------------------------------
__global__ void prep_all(const float* __restrict__ cb) {
    int id = blockIdx.x * blockDim.x + threadIdx.x;
    if (id < MLVL * 64 * 512) {
        int u    = id & 511;
        int half = u >> 8;
        int nt   = (u >> 5) & 7;
        int lane = u & 31;
        int s    = (id >> 9) & 63;
        int lvl  = id >> 15;
        int nc = s >> 3, kb = s & 7;
        int n  = nc * 128 + half * 64 + nt * 8 + (lane >> 2);
        int k0 = kb * 32 + (lane & 3) * 2;
        const float* row = cb + ((size_t)lvl * KCODES + n) * DDIM;
        uint4 v;
        v.x = pkhf(row[k0]      * SB_SC, row[k0 + 1]  * SB_SC);
        v.y = pkhf(row[k0 + 8]  * SB_SC, row[k0 + 9]  * SB_SC);
        v.z = pkhf(row[k0 + 16] * SB_SC, row[k0 + 17] * SB_SC);
        v.w = pkhf(row[k0 + 24] * SB_SC, row[k0 + 25] * SB_SC);
        g_cbfrag[id] = v;
    }
    int warp = id >> 5;
    int lane = id & 31;
    if (warp < MLVL * KCODES) {
        const float* row = cb + (size_t)warp * DDIM;
        double s = 0.0;
#pragma unroll
        for (int m = 0; m < DDIM / 32; m++) {
            float v = row[lane + 32 * m];
            s += (double)v * (double)v;
        }
#pragma unroll
        for (int off = 16; off; off >>= 1) s += __shfl_xor_sync(0xffffffffu, s, off);
        if (lane == 0) g_e2[warp] = (float)s;
    }
}

// ---------------------------------------------------------------------------
struct Top3 { float d0, d1, d2; int i0, i1, i2; };
static __device__ __forceinline__ void t3_insert(Top3& T, float d, int idx) {
    if (d < T.d2) {
        if (d < T.d1) {
            T.d2 = T.d1; T.i2 = T.i1;
            if (d < T.d0) { T.d1 = T.d0; T.i1 = T.i0; T.d0 = d; T.i0 = idx; }
            else          { T.d1 = d;    T.i1 = idx; }
        } else { T.d2 = d; T.i2 = idx; }
    }
}
static __device__ __forceinline__ void t4_insert(float* d, int* i, float nd, int ni) {
    bool l3 = (nd < d[3]) || (nd == d[3] && ni < i[3]);
    if (!l3) return;
    bool l2 = (nd < d[2]) || (nd == d[2] && ni < i[2]);
    bool l1 = (nd < d[1]) || (nd == d[1] && ni < i[1]);
    bool l0 = (nd < d[0]) || (nd == d[0] && ni < i[0]);
    if (l0)      { d[3]=d[2]; i[3]=i[2]; d[2]=d[1]; i[2]=i[1]; d[1]=d[0]; i[1]=i[0]; d[0]=nd; i[0]=ni; }
    else if (l1) { d[3]=d[2]; i[3]=i[2]; d[2]=d[1]; i[2]=i[1]; d[1]=nd; i[1]=ni; }
    else if (l2) { d[3]=d[2]; i[3]=i[2]; d[2]=nd; i[2]=ni; }
    else         { d[3]=nd; i[3]=ni; }
}

// ---------------------------------------------------------------------------
// Templated body (round-12 chassis, f16-accum HMMA screen, complete rescue).
//   TMLOC=128: 8 M-warps x 2 N-segments;  TMLOC=64: 4 M-warps x 4 N-segments.
// ---------------------------------------------------------------------------
template<int TMLOC>
static __device__ __forceinline__ void rvq_body(
    const float* __restrict__ X, const float* __restrict__ CB,
    float* __restrict__ Y, char* smem, long long tokenBase) {
    constexpr int NWM  = TMLOC / 16;
    constexpr int NSEG = 16 / NWM;
    constexpr int NTT  = 16 / NSEG;
    constexpr int CSEG = 128 / NSEG;

    float*  Rsh     = (float*)(smem + OFF_RSH);
    uint4*  Af      = (uint4*)(smem + OFF_AFRAG);
    uint4*  Bb      = (uint4*)(smem + OFF_BBUF);
    float4* htd     = (float4*)(smem + OFF_HTD);
    int4*   hti     = (int4*)(smem + OFF_HTI);
    double* redD    = (double*)(smem + OFF_REDD);
    float*  e2Sh    = (float*)(smem + OFF_E2);
    float*  r2Sh    = (float*)(smem + OFF_R2);
    int*    bestI   = (int*)(smem + OFF_BEST);
    int*    candTok = (int*)(smem + OFF_CTOK);
    int*    candCnt = (int*)(smem + OFF_CCNT);

    const int tid  = threadIdx.x;
    const int wid  = tid >> 5;
    const int lane = tid & 31;
    const int wm   = wid % NWM;
    const int wn   = wid / NWM;
    const int bOff = (CSEG == 64) ? wn * 256 : ((wn >> 1) * 256 + (wn & 1) * 128);
    const int g    = lane >> 2;
    const int tg2  = (lane & 3) * 2;
    const float* Xblk = X + tokenBase * DDIM;
    const float INF = __int_as_float(0x7f800000);

    // ---- load X tile -----------------------------------------------------
    for (int idx = tid; idx < TMLOC * (DDIM / 4); idx += THREADS) {
        int t = idx >> 6, dq = (idx & 63) << 2;
        *(float4*)(Rsh + t * RS + dq) = *(const float4*)(Xblk + (long long)t * DDIM + dq);
    }
    __syncthreads();

    // ---- initial r2 (fp64 -> fp32) ---------------------------------------
    {
        int t = tid >> 2, h = tid & 3;
        if (t < TMLOC) {
            const float* rr = Rsh + t * RS + h * 64;
            double s = 0.0;
            for (int k = 0; k < 64; k++) { float f = rr[k]; s += (double)f * f; }
            redD[tid] = s;
        }
        __syncthreads();
        if (t < TMLOC && !h)
            r2Sh[t] = (float)(redD[tid] + redD[tid + 1] + redD[tid + 2] + redD[tid + 3]);
    }
    __syncthreads();

    double commitAcc = 0.0;

    for (int lvl = 0; lvl < MLVL; lvl++) {
        // ---- level setup: e2, candCnt, A f16 fragments --------------------
        if (tid == 0) *candCnt = 0;
        for (int i = tid; i < KCODES; i += THREADS) e2Sh[i] = g_e2[lvl * KCODES + i];
        for (int idx = tid; idx < TMLOC * 32; idx += THREADS) {
            int mt = idx >> 9, ks = (idx >> 5) & 15, ln = idx & 31;
            int m0 = mt * 16 + (ln >> 2);
            int k0 = ks * 16 + (ln & 3) * 2;
            const float* ra = Rsh + m0 * RS;
            const float* rb = Rsh + (m0 + 8) * RS;
            uint4 v;
            v.x = pkhf(ra[k0],     ra[k0 + 1]);
            v.y = pkhf(rb[k0],     rb[k0 + 1]);
            v.z = pkhf(ra[k0 + 8], ra[k0 + 9]);
            v.w = pkhf(rb[k0 + 8], rb[k0 + 9]);
            Af[idx] = v;
        }
        __syncthreads();   // Af ready; ring overlays dead below

        const float r2a = r2Sh[wm * 16 + g];
        const float r2b = r2Sh[wm * 16 + g + 8];

        Top3 T[2];
#pragma unroll
        for (int q = 0; q < 2; q++) { T[q].d0 = T[q].d1 = T[q].d2 = INF; T[q].i0 = T[q].i1 = T[q].i2 = 0x7fffffff; }

        const uint4* gb = g_cbfrag + (size_t)lvl * 64 * 512;

        // ---- prologue: prefetch stages 0,1 --------------------------------
        cpasync16(Bb + 0 * 512 + tid, gb + 0 * 512 + tid);
        CP_COMMIT();
        cpasync16(Bb + 1 * 512 + tid, gb + 1 * 512 + tid);
        CP_COMMIT();

        uint32_t acc[NTT][2];   // f16x2 accumulators
        int cur = 0;

        for (int sl = 0; sl < 64; sl++) {
            const int kb = sl & 7;
            CP_WAIT(1);
            __syncthreads();
            if (sl + 2 < 64) {
                int nb = cur == 0 ? 2 : cur - 1;
                cpasync16(Bb + nb * 512 + tid, gb + (size_t)(sl + 2) * 512 + tid);
            }
            CP_COMMIT();

            if (kb == 0) {
#pragma unroll
                for (int nt = 0; nt < NTT; nt++) { acc[nt][0] = 0u; acc[nt][1] = 0u; }
            }

            uint4 A0 = Af[(wm * 16 + kb * 2 + 0) * 32 + lane];
            uint4 A1 = Af[(wm * 16 + kb * 2 + 1) * 32 + lane];
            const uint4* Bp = Bb + cur * 512 + bOff + lane;
            uint4 Bv[NTT];
#pragma unroll
            for (int nt = 0; nt < NTT; nt++) Bv[nt] = Bp[nt * 32];
#pragma unroll
            for (int nt = 0; nt < NTT; nt++) mma16816h(acc[nt], A0, Bv[nt].x, Bv[nt].y);
#pragma unroll
            for (int nt = 0; nt < NTT; nt++) mma16816h(acc[nt], A1, Bv[nt].z, Bv[nt].w);

            // ---- per-chunk epilogue: dist + top-3 streaming ----------------
            if (kb == 7) {
                const int nc = sl >> 3;
#pragma unroll
                for (int nt = 0; nt < NTT; nt++) {
                    int nbase = nc * 128 + wn * CSEG + nt * 8 + tg2;
                    float2 e2p = *(const float2*)&e2Sh[nbase];
                    float2 dl = __half22float2(*(__half2*)&acc[nt][0]);  // row g
                    float2 dh = __half22float2(*(__half2*)&acc[nt][1]);  // row g+8
                    t3_insert(T[0], fmaf(M2D, dl.x, r2a + e2p.x), nbase);
                    t3_insert(T[0], fmaf(M2D, dl.y, r2a + e2p.y), nbase + 1);
                    t3_insert(T[1], fmaf(M2D, dh.x, r2b + e2p.x), nbase);
                    t3_insert(T[1], fmaf(M2D, dh.y, r2b + e2p.y), nbase + 1);
                }
            }
            cur = cur == 2 ? 0 : cur + 1;
        } // slices

        __syncthreads();   // compute done before htd/hti overlay ring

        // ---- quad merge + saturation bound, publish per-segment -----------
#pragma unroll
        for (int q = 0; q < 2; q++) {
            // lane truncation bound: min over quad of each lane's kept 3rd
            float l3 = T[q].d2;
            l3 = fminf(l3, __shfl_xor_sync(0xffffffffu, l3, 1));
            l3 = fminf(l3, __shfl_xor_sync(0xffffffffu, l3, 2));

            float md[4] = { T[q].d0, T[q].d1, T[q].d2, INF };
            int   mi[4] = { T[q].i0, T[q].i1, T[q].i2, 0x7fffffff };
#pragma unroll
            for (int off = 1; off <= 2; off <<= 1) {
                float od[4]; int oi[4];
#pragma unroll
                for (int j = 0; j < 4; j++) {
                    od[j] = __shfl_xor_sync(0xffffffffu, md[j], off);
                    oi[j] = __shfl_xor_sync(0xffffffffu, mi[j], off);
                }
#pragma unroll
                for (int j = 0; j < 4; j++) t4_insert(md, mi, od[j], oi[j]);
            }
            if ((lane & 3) == 0) {
                int tok = wm * 16 + g + q * 8;
                // .w = satT: upper bound on anything truncated in this segment
                float satT = fminf(md[3], l3);
                htd[wn * TMLOC + tok] = make_float4(md[0], md[1], md[2], satT);
                hti[wn * TMLOC + tok] = make_int4(mi[0], mi[1], mi[2], mi[3]);
            }
        }
        __syncthreads();

        // ---- decision: top-2 over NSEG*4 (+ saturation flags) --------------
        if (tid < TMLOC) {
            float4 ds[NSEG]; int4 is[NSEG];
#pragma unroll
            for (int q = 0; q < NSEG; q++) { ds[q] = htd[q * TMLOC + tid]; is[q] = hti[q * TMLOC + tid]; }
            float d0 = INF, d1 = INF; int i0v = 0x7fffffff, i1v = 0x7fffffff;
#pragma unroll
            for (int q = 0; q < NSEG; q++) {
                const float* dp = &ds[q].x;
                const int*   ip = &is[q].x;
#pragma unroll
                for (int j = 0; j < 4; j++) {
                    float d = dp[j]; int i = ip[j];
                    if (d < d0 || (d == d0 && i < i0v)) {
                        d1 = d0; i1v = i0v; d0 = d; i0v = i;
                    } else if (d < d1 || (d == d1 && i < i1v)) {
                        d1 = d; i1v = i;
                    }
                }
            }
            if (d1 >= d0 + MARGIN) {
                bestI[tid] = i0v;
            } else {
                int sat = 0;
#pragma unroll
                for (int q = 0; q < NSEG; q++)
                    if (ds[q].w < d0 + MARGIN) sat |= 1 << q;
                int p = atomicAdd(candCnt, 1);
                candTok[p] = tid | (sat << 16);
            }
        }
        __syncthreads();

        // ---- rescue: exact fp32 union (+ rare saturated-segment scans) ----
        {
            int cnt = *candCnt;
            for (int e = wid; e < cnt; e += 16) {
                int ent = candTok[e];
                int tok = ent & 0xffff, sat = ent >> 16;
                float r2t = r2Sh[tok];
                const float* rrow = Rsh + tok * RS + lane * 8;
                float bd = INF; int bi = 0x7fffffff;
#pragma unroll
                for (int q = 0; q < NSEG; q++) {
                    int4 cs = hti[q * TMLOC + tok];
                    const int* ip = &cs.x;
#pragma unroll
                    for (int j = 0; j < 4; j++) {
                        int idx = ip[j];
                        if (idx >= KCODES) continue;
                        const float* crow = CB + ((size_t)lvl * KCODES + idx) * DDIM + lane * 8;
                        float p = 0.f;
#pragma unroll
                        for (int u = 0; u < 8; u++) p = fmaf(rrow[u], crow[u], p);
#pragma unroll
                        for (int o = 16; o; o >>= 1) p += __shfl_xor_sync(0xffffffffu, p, o);
                        float dd = fmaf(-2.f, p, r2t + e2Sh[idx]);
                        if (dd < bd || (dd == bd && idx < bi)) { bd = dd; bi = idx; }
                    }
                }
                // full exact scan of saturated segments (rare)
                for (int q = 0; q < NSEG; q++) {
                    if (!((sat >> q) & 1)) continue;
                    for (int nc2 = 0; nc2 < 8; nc2++) {
                        for (int j = 0; j < CSEG; j++) {
                            int idx = nc2 * 128 + q * CSEG + j;
                            const float* crow = CB + ((size_t)lvl * KCODES + idx) * DDIM + lane * 8;
                            float p = 0.f;
#pragma unroll
                            for (int u = 0; u < 8; u++) p = fmaf(rrow[u], crow[u], p);
#pragma unroll
                            for (int o = 16; o; o >>= 1) p += __shfl_xor_sync(0xffffffffu, p, o);
                            float dd = fmaf(-2.f, p, r2t + e2Sh[idx]);
                            if (dd < bd || (dd == bd && idx < bi)) { bd = dd; bi = idx; }
                        }
                    }
                }
                if (lane == 0) bestI[tok] = bi;
            }
        }
        __syncthreads();

        // ---- residual update + new r2 + commit (4 threads / token) --------
        {
            int t = tid >> 2, h = tid & 3;
            if (t < TMLOC) {
                int b = bestI[t];
                const float* qv = CB + ((size_t)lvl * KCODES + b) * DDIM + h * 64;
                float* rr = Rsh + t * RS + h * 64;
                double ss = 0.0;
                for (int k = 0; k < 64; k += 4) {
                    float4 q4 = *(const float4*)(qv + k);
                    float n0 = rr[k]     - q4.x;
                    float n1 = rr[k + 1] - q4.y;
                    float n2 = rr[k + 2] - q4.z;
                    float n3 = rr[k + 3] - q4.w;
                    rr[k] = n0; rr[k + 1] = n1; rr[k + 2] = n2; rr[k + 3] = n3;
                    ss += (double)n0 * n0 + (double)n1 * n1
                        + (double)n2 * n2 + (double)n3 * n3;
                }
                redD[tid] = ss;
                commitAcc += ss;
            }
            __syncthreads();
            if (t < TMLOC && !h)
                r2Sh[t] = (float)(redD[tid] + redD[tid + 1] + redD[tid + 2] + redD[tid + 3]);
        }
        __syncthreads();
    } // levels

    // ---- y = x - r_final ---------------------------------------------------
    for (int idx = tid; idx < TMLOC * (DDIM / 4); idx += THREADS) {
        int t = idx >> 6, dq = (idx & 63) << 2;
        float4 xv = *(const float4*)(Xblk + (long long)t * DDIM + dq);
        const float* rr = Rsh + t * RS + dq;
        float4 y;
        y.x = xv.x - rr[0]; y.y = xv.y - rr[1];
        y.z = xv.z - rr[2]; y.w = xv.w - rr[3];
        *(float4*)(Y + (tokenBase + t) * DDIM + dq) = y;
    }

    // ---- deterministic per-block commit partial ----------------------------
    redD[tid] = commitAcc;
    for (int s = THREADS / 2; s > 0; s >>= 1) {
        __syncthreads();
        if (tid < s) redD[tid] += redD[tid + s];
    }
    if (tid == 0) g_commitPartial[blockIdx.x] = redD[0];
}

// ---------------------------------------------------------------------------
__global__ __launch_bounds__(THREADS, 1)
void rvq_mma(const float* __restrict__ X, const float* __restrict__ CB,
             float* __restrict__ Y) {
    extern __shared__ char smem[];
    if (blockIdx.x < NBIG) {
        rvq_body<128>(X, CB, Y, smem, (long long)blockIdx.x * 128);
    } else {
        rvq_body<64>(X, CB, Y, smem,
                     (long long)NBIG * 128 + (long long)(blockIdx.x - NBIG) * 64);
    }
}

// ---------------------------------------------------------------------------
__global__ void finalize_kernel(float* __restrict__ Y, int out_size) {
    __shared__ double sd[1024];
    int tid = threadIdx.x;
    sd[tid] = (tid < GRID) ? g_commitPartial[tid] : 0.0;
    for (int s = 512; s > 0; s >>= 1) {
        __syncthreads();
        if (tid < s) sd[tid] += sd[tid + s];
    }
    if (tid == 0) {
        double mean = sd[0] / (double)((long long)NTOK * DDIM);
        float commit = (float)(0.25 * mean);
        long long numel = (long long)NTOK * DDIM;
        for (long long j = numel; j < (long long)out_size; j++) Y[j] = commit;
    }
}

extern "C" void kernel_launch(void* const* d_in, const int* in_sizes, int n_in,
                              void* d_out, int out_size) {
    const float* X  = (const float*)d_in[0];
    const float* CB = (const float*)d_in[1];
    float* Y = (float*)d_out;

    cudaFuncSetAttribute(rvq_mma, cudaFuncAttributeMaxDynamicSharedMemorySize,
                         SMEM_TOTAL);

    prep_all<<<512, 256>>>(CB);
    rvq_mma<<<GRID, THREADS, SMEM_TOTAL>>>(X, CB, Y);
    finalize_kernel<<<1, 1024>>>(Y, out_size);
}

// round 14
// speedup vs baseline: 1.2063x; 1.2063x over previous
#include <cuda_runtime.h>
#include <cuda_bf16.h>
#include <cstdint>

// Problem constants
#define NTOK    65536
#define DDIM    256
#define KCODES  1024
#define MLVL    4
#define THREADS 512
#define RS      260            // fp32 residual row stride (floats)
#define MARGIN  4e-4f
// Mixed tiling: 432 big tiles (128 tok) + 160 small tiles (64 tok) = 592 = 4*148
#define NBIG    432
#define NSMALL  160
#define GRID    (NBIG + NSMALL)

// SMEM byte offsets (dynamic smem, total 228880)
#define OFF_RSH    0            // 133120: [128][260] fp32 residual
#define OFF_AFRAG  133120       // 65536:  A fragments [mt][ks16][lane32] uint4
#define OFF_BBUF   198656       // 24576:  3 x 8KB B slices (ring)
// Overlays inside BBUF (dead while ring unused; barrier-separated):
#define OFF_HTD    198656       // float4 topDist[seg][tok] (8192)
#define OFF_HTI    206848       // int4   topIdx [seg][tok] (8192)
#define OFF_CIDX   215040       // int4   candIdx[128]      (2048)
#define OFF_REDD   217088       // double redD[512]         (4096)
#define OFF_E2     223232       // 4096
#define OFF_R2     227328       // 512
#define OFF_BEST   227840       // 512
#define OFF_CTOK   228352       // 512
#define OFF_CCNT   228864       // 16
#define SMEM_TOTAL 228880

__device__ float  g_e2[MLVL * KCODES];
__device__ double g_commitPartial[GRID];
// B fragments: [lvl][slice(64)][512 x uint4]  (slice = nc*8 + kb, 8KB each)
__device__ uint4  g_cbfrag[MLVL * 64 * 512];

static __device__ __forceinline__ uint32_t pkbf(float a, float b) {
    __nv_bfloat162 h = __floats2bfloat162_rn(a, b);
    return *reinterpret_cast<uint32_t*>(&h);
}
static __device__ __forceinline__ uint32_t pkbf2(float2 p) {
    __nv_bfloat162 h = __floats2bfloat162_rn(p.x, p.y);
    return *reinterpret_cast<uint32_t*>(&h);
}
static __device__ __forceinline__ void mma16816(float* c, const uint4& A,
                                                uint32_t b0, uint32_t b1) {
    asm volatile(
        "mma.sync.aligned.m16n8k16.row.col.f32.bf16.bf16.f32 "
        "{%0,%1,%2,%3}, {%4,%5,%6,%7}, {%8,%9}, {%0,%1,%2,%3};"
        : "+f"(c[0]), "+f"(c[1]), "+f"(c[2]), "+f"(c[3])
        : "r"(A.x), "r"(A.y), "r"(A.z), "r"(A.w), "r"(b0), "r"(b1));
}
static __device__ __forceinline__ void cpasync16(void* dst, const void* src) {
    uint32_t d = (uint32_t)__cvta_generic_to_shared(dst);
    asm volatile("cp.async.cg.shared.global [%0], [%1], 16;" :: "r"(d), "l"(src));
}
#define CP_COMMIT() asm volatile("cp.async.commit_group;")
#define CP_WAIT(n)  asm volatile("cp.async.wait_group %0;" :: "n"(n))

// ---------------------------------------------------------------------------
// Merged prep: codebook bf16 fragment pack + per-warp e2 row (fp64).
// ---------------------------------------------------------------------------
__global__ void prep_all(const float* __restrict__ cb) {
    int id = blockIdx.x * blockDim.x + threadIdx.x;
    if (id < MLVL * 64 * 512) {
        int u    = id & 511;
        int half = u >> 8;
        int nt   = (u >> 5) & 7;
        int lane = u & 31;
        int s    = (id >> 9) & 63;
        int lvl  = id >> 15;
        int nc = s >> 3, kb = s & 7;
        int n  = nc * 128 + half * 64 + nt * 8 + (lane >> 2);
        int k0 = kb * 32 + (lane & 3) * 2;
        const float* row = cb + ((size_t)lvl * KCODES + n) * DDIM;
        uint4 v;
        v.x = pkbf(row[k0],      row[k0 + 1]);
        v.y = pkbf(row[k0 + 8],  row[k0 + 9]);
        v.z = pkbf(row[k0 + 16], row[k0 + 17]);
        v.w = pkbf(row[k0 + 24], row[k0 + 25]);
        g_cbfrag[id] = v;
    }
    int warp = id >> 5;
    int lane = id & 31;
    if (warp < MLVL * KCODES) {
        const float* row = cb + (size_t)warp * DDIM;
        double s = 0.0;
#pragma unroll
        for (int m = 0; m < DDIM / 32; m++) {
            float v = row[lane + 32 * m];
            s += (double)v * (double)v;
        }
#pragma unroll
        for (int off = 16; off; off >>= 1) s += __shfl_xor_sync(0xffffffffu, s, off);
        if (lane == 0) g_e2[warp] = (float)s;
    }
}

// ---------------------------------------------------------------------------
struct Top3 { float d0, d1, d2; int i0, i1, i2; };
static __device__ __forceinline__ void t3_insert(Top3& T, float d, int idx) {
    if (d < T.d2) {
        if (d < T.d1) {
            T.d2 = T.d1; T.i2 = T.i1;
            if (d < T.d0) { T.d1 = T.d0; T.i1 = T.i0; T.d0 = d; T.i0 = idx; }
            else          { T.d1 = d;    T.i1 = idx; }
        } else { T.d2 = d; T.i2 = idx; }
    }
}
static __device__ __forceinline__ void t4_insert(float* d, int* i, float nd, int ni) {
    bool l3 = (nd < d[3]) || (nd == d[3] && ni < i[3]);
    if (!l3) return;
    bool l2 = (nd < d[2]) || (nd == d[2] && ni < i[2]);
    bool l1 = (nd < d[1]) || (nd == d[1] && ni < i[1]);
    bool l0 = (nd < d[0]) || (nd == d[0] && ni < i[0]);
    if (l0)      { d[3]=d[2]; i[3]=i[2]; d[2]=d[1]; i[2]=i[1]; d[1]=d[0]; i[1]=i[0]; d[0]=nd; i[0]=ni; }
    else if (l1) { d[3]=d[2]; i[3]=i[2]; d[2]=d[1]; i[2]=i[1]; d[1]=nd; i[1]=ni; }
    else if (l2) { d[3]=d[2]; i[3]=i[2]; d[2]=nd; i[2]=ni; }
    else         { d[3]=nd; i[3]=ni; }
}

// ---------------------------------------------------------------------------
// Templated body (round-12 chassis: bf16 f32-acc HMMA screen + margin +
// exact-fp32 rescue; 3-stage cp.async ring; early B-prefetch per level).
// ---------------------------------------------------------------------------
template<int TMLOC>
static __device__ __forceinline__ void rvq_body(
    const float* __restrict__ X, const float* __restrict__ CB,
    float* __restrict__ Y, char* smem, long long tokenBase) {
    constexpr int NWM  = TMLOC / 16;    // warps along M (8 or 4)
    constexpr int NSEG = 16 / NWM;      // N segments (2 or 4)
    constexpr int NTT  = 16 / NSEG;     // ntiles per warp (8 or 4)
    constexpr int CSEG = 128 / NSEG;    // codes per segment (64 or 32)

    float*  Rsh     = (float*)(smem + OFF_RSH);
    uint4*  Af      = (uint4*)(smem + OFF_AFRAG);
    uint4*  Bb      = (uint4*)(smem + OFF_BBUF);
    float4* htd     = (float4*)(smem + OFF_HTD);
    int4*   hti     = (int4*)(smem + OFF_HTI);
    int4*   candIdx = (int4*)(smem + OFF_CIDX);
    double* redD    = (double*)(smem + OFF_REDD);
    float*  e2Sh    = (float*)(smem + OFF_E2);
    float*  r2Sh    = (float*)(smem + OFF_R2);
    int*    bestI   = (int*)(smem + OFF_BEST);
    int*    candTok = (int*)(smem + OFF_CTOK);
    int*    candCnt = (int*)(smem + OFF_CCNT);

    const int tid  = threadIdx.x;
    const int wid  = tid >> 5;
    const int lane = tid & 31;
    const int wm   = wid % NWM;
    const int wn   = wid / NWM;
    const int bOff = (CSEG == 64) ? wn * 256 : ((wn >> 1) * 256 + (wn & 1) * 128);
    const int g    = lane >> 2;
    const int tg2  = (lane & 3) * 2;
    const float* Xblk = X + tokenBase * DDIM;
    const float INF = __int_as_float(0x7f800000);

    // ---- load X tile -----------------------------------------------------
    for (int idx = tid; idx < TMLOC * (DDIM / 4); idx += THREADS) {
        int t = idx >> 6, dq = (idx & 63) << 2;
        *(float4*)(Rsh + t * RS + dq) = *(const float4*)(Xblk + (long long)t * DDIM + dq);
    }
    __syncthreads();

    // ---- initial r2 (fp64 -> fp32) ---------------------------------------
    {
        int t = tid >> 2, h = tid & 3;
        if (t < TMLOC) {
            const float* rr = Rsh + t * RS + h * 64;
            double s = 0.0;
            for (int k = 0; k < 64; k++) { float f = rr[k]; s += (double)f * f; }
            redD[tid] = s;
        }
        __syncthreads();
        if (t < TMLOC && !h)
            r2Sh[t] = (float)(redD[tid] + redD[tid + 1] + redD[tid + 2] + redD[tid + 3]);
    }
    __syncthreads();

    // level-0 prologue prefetch (stages 0,1 of level 0)
    {
        const uint4* gb0 = g_cbfrag;
        cpasync16(Bb + 0 * 512 + tid, gb0 + 0 * 512 + tid);
        CP_COMMIT();
        cpasync16(Bb + 1 * 512 + tid, gb0 + 1 * 512 + tid);
        CP_COMMIT();
    }

    double commitAcc = 0.0;

    for (int lvl = 0; lvl < MLVL; lvl++) {
        // ---- level setup: e2, candCnt, A fragments (bf16) ----------------
        if (tid == 0) *candCnt = 0;
        for (int i = tid; i < KCODES; i += THREADS) e2Sh[i] = g_e2[lvl * KCODES + i];
        for (int idx = tid; idx < TMLOC * 32; idx += THREADS) {
            int mt = idx >> 9, ks = (idx >> 5) & 15, ln = idx & 31;
            int m0 = mt * 16 + (ln >> 2);
            int k0 = ks * 16 + (ln & 3) * 2;
            const float* ra = Rsh + m0 * RS;
            const float* rb = Rsh + (m0 + 8) * RS;
            uint4 v;
            v.x = pkbf2(*(const float2*)(ra + k0));
            v.y = pkbf2(*(const float2*)(rb + k0));
            v.z = pkbf2(*(const float2*)(ra + k0 + 8));
            v.w = pkbf2(*(const float2*)(rb + k0 + 8));
            Af[idx] = v;
        }
        __syncthreads();   // Af ready; ring stages 0,1 already in flight

        const float r2a = r2Sh[wm * 16 + g];
        const float r2b = r2Sh[wm * 16 + g + 8];

        Top3 T[2];
#pragma unroll
        for (int q = 0; q < 2; q++) { T[q].d0 = T[q].d1 = T[q].d2 = INF; T[q].i0 = T[q].i1 = T[q].i2 = 0x7fffffff; }

        const uint4* gb = g_cbfrag + (size_t)lvl * 64 * 512;

        float acc[NTT][4];
        int cur = 0;

        for (int sl = 0; sl < 64; sl++) {
            const int kb = sl & 7;
            CP_WAIT(1);        // stage sl landed
            __syncthreads();   // visible to all; all done with buf (sl-1)%3
            if (sl + 2 < 64) {
                int nb = cur == 0 ? 2 : cur - 1;   // (sl+2)%3
                cpasync16(Bb + nb * 512 + tid, gb + (size_t)(sl + 2) * 512 + tid);
            }
            CP_COMMIT();       // unconditional: uniform group indexing

            if (kb == 0) {
#pragma unroll
                for (int nt = 0; nt < NTT; nt++)
#pragma unroll
                    for (int c = 0; c < 4; c++) acc[nt][c] = 0.f;
            }

            uint4 A0 = Af[(wm * 16 + kb * 2 + 0) * 32 + lane];
            uint4 A1 = Af[(wm * 16 + kb * 2 + 1) * 32 + lane];
            const uint4* Bp = Bb + cur * 512 + bOff + lane;
            uint4 Bv[NTT];
#pragma unroll
            for (int nt = 0; nt < NTT; nt++) Bv[nt] = Bp[nt * 32];
#pragma unroll
            for (int nt = 0; nt < NTT; nt++) mma16816(acc[nt], A0, Bv[nt].x, Bv[nt].y);
#pragma unroll
            for (int nt = 0; nt < NTT; nt++) mma16816(acc[nt], A1, Bv[nt].z, Bv[nt].w);

            // ---- per-chunk epilogue: dist + top-3 streaming --------------
            if (kb == 7) {
                const int nc = sl >> 3;
#pragma unroll
                for (int nt = 0; nt < NTT; nt++) {
                    int nbase = nc * 128 + wn * CSEG + nt * 8 + tg2;
                    float2 e2p = *(const float2*)&e2Sh[nbase];
                    t3_insert(T[0], fmaf(-2.f, acc[nt][0], r2a + e2p.x), nbase);
                    t3_insert(T[0], fmaf(-2.f, acc[nt][1], r2a + e2p.y), nbase + 1);
                    t3_insert(T[1], fmaf(-2.f, acc[nt][2], r2b + e2p.x), nbase);
                    t3_insert(T[1], fmaf(-2.f, acc[nt][3], r2b + e2p.y), nbase + 1);
                }
            }
            cur = cur == 2 ? 0 : cur + 1;
        } // slices

        __syncthreads();   // compute done before htd/hti overlay ring

        // ---- quad merge, publish per-(segment,token) top-4 to SMEM -------
#pragma unroll
        for (int q = 0; q < 2; q++) {
            float md[4] = { T[q].d0, T[q].d1, T[q].d2, INF };
            int   mi[4] = { T[q].i0, T[q].i1, T[q].i2, 0x7fffffff };
#pragma unroll
            for (int off = 1; off <= 2; off <<= 1) {
                float od[4]; int oi[4];
#pragma unroll
                for (int j = 0; j < 4; j++) {
                    od[j] = __shfl_xor_sync(0xffffffffu, md[j], off);
                    oi[j] = __shfl_xor_sync(0xffffffffu, mi[j], off);
                }
#pragma unroll
                for (int j = 0; j < 4; j++) t4_insert(md, mi, od[j], oi[j]);
            }
            if ((lane & 3) == 0) {
                int tok = wm * 16 + g + q * 8;
                htd[wn * TMLOC + tok] = make_float4(md[0], md[1], md[2], md[3]);
                hti[wn * TMLOC + tok] = make_int4(mi[0], mi[1], mi[2], mi[3]);
            }
        }
        __syncthreads();

        // ---- cross-segment merge + decision (one thread per token) -------
        if (tid < TMLOC) {
            float4 d0 = htd[tid];  int4 i0 = hti[tid];
            float md[4] = { d0.x, d0.y, d0.z, d0.w };
            int   mi[4] = { i0.x, i0.y, i0.z, i0.w };
#pragma unroll
            for (int h = 1; h < NSEG; h++) {
                float4 dh = htd[h * TMLOC + tid];  int4 ih = hti[h * TMLOC + tid];
                t4_insert(md, mi, dh.x, ih.x);
                t4_insert(md, mi, dh.y, ih.y);
                t4_insert(md, mi, dh.z, ih.z);
                t4_insert(md, mi, dh.w, ih.w);
            }
            if (md[1] >= md[0] + MARGIN) {
                bestI[tid] = mi[0];
            } else {
                int p = atomicAdd(candCnt, 1);
                candTok[p] = tid;
                candIdx[tid] = make_int4(mi[0], mi[1], mi[2], mi[3]);
            }
        }
        __syncthreads();

        // ---- rescue: exact fp32 dots for flagged tokens (warp per entry) -
        {
            int cnt = *candCnt;
            for (int e = wid; e < cnt; e += 16) {
                int tok = candTok[e];
                int4 cs = candIdx[tok];
                float r2t = r2Sh[tok];
                const float* rrow = Rsh + tok * RS + lane * 8;
                float bd = INF; int bi = 0x7fffffff;
#pragma unroll
                for (int j = 0; j < 4; j++) {
                    int idx = (&cs.x)[j];
                    const float* crow = CB + ((size_t)lvl * KCODES + idx) * DDIM + lane * 8;
                    float p = 0.f;
#pragma unroll
                    for (int u = 0; u < 8; u++) p = fmaf(rrow[u], crow[u], p);
#pragma unroll
                    for (int o = 16; o; o >>= 1) p += __shfl_xor_sync(0xffffffffu, p, o);
                    float dd = fmaf(-2.f, p, r2t + e2Sh[idx]);
                    if (dd < bd || (dd == bd && idx < bi)) { bd = dd; bi = idx; }
                }
                if (lane == 0) bestI[tok] = bi;
            }
        }
        __syncthreads();

        // ---- EARLY prefetch of next level's stages 0,1 ---------------------
        // Stages 0,1 occupy the htd/hti overlay region, whose last read was
        // the rescue phase above (barrier-separated). Issuing here hides the
        // L2 latency under the residual update + A-build phases.
        if (lvl + 1 < MLVL) {
            const uint4* gbn = g_cbfrag + (size_t)(lvl + 1) * 64 * 512;
            cpasync16(Bb + 0 * 512 + tid, gbn + 0 * 512 + tid);
            CP_COMMIT();
            cpasync16(Bb + 1 * 512 + tid, gbn + 1 * 512 + tid);
            CP_COMMIT();
        }

        // ---- residual update + new r2 + commit (4 threads / token) -------
        {
            int t = tid >> 2, h = tid & 3;
            if (t < TMLOC) {
                int b = bestI[t];
                const float* qv = CB + ((size_t)lvl * KCODES + b) * DDIM + h * 64;
                float* rr = Rsh + t * RS + h * 64;
                double ss = 0.0;
                for (int k = 0; k < 64; k += 4) {
                    float4 q4 = *(const float4*)(qv + k);
                    float n0 = rr[k]     - q4.x;
                    float n1 = rr[k + 1] - q4.y;
                    float n2 = rr[k + 2] - q4.z;
                    float n3 = rr[k + 3] - q4.w;
                    rr[k] = n0; rr[k + 1] = n1; rr[k + 2] = n2; rr[k + 3] = n3;
                    ss += (double)n0 * n0 + (double)n1 * n1
                        + (double)n2 * n2 + (double)n3 * n3;
                }
                redD[tid] = ss;
                commitAcc += ss;
            }
            __syncthreads();
            if (t < TMLOC && !h)
                r2Sh[t] = (float)(redD[tid] + redD[tid + 1] + redD[tid + 2] + redD[tid + 3]);
        }
        __syncthreads();
    } // levels

    // ---- y = x - r_final ---------------------------------------------------
    for (int idx = tid; idx < TMLOC * (DDIM / 4); idx += THREADS) {
        int t = idx >> 6, dq = (idx & 63) << 2;
        float4 xv = *(const float4*)(Xblk + (long long)t * DDIM + dq);
        const float* rr = Rsh + t * RS + dq;
        float4 y;
        y.x = xv.x - rr[0]; y.y = xv.y - rr[1];
        y.z = xv.z - rr[2]; y.w = xv.w - rr[3];
        *(float4*)(Y + (tokenBase + t) * DDIM + dq) = y;
    }
    CP_WAIT(0);   // drain the speculative last-level prefetch state

    // ---- deterministic per-block commit partial ----------------------------
    redD[tid] = commitAcc;
    for (int s = THREADS / 2; s > 0; s >>= 1) {
        __syncthreads();
        if (tid < s) redD[tid] += redD[tid + s];
    }
    if (tid == 0) g_commitPartial[blockIdx.x] = redD[0];
}

// ---------------------------------------------------------------------------
__global__ __launch_bounds__(THREADS, 1)
void rvq_mma(const float* __restrict__ X, const float* __restrict__ CB,
             float* __restrict__ Y) {
    extern __shared__ char smem[];
    if (blockIdx.x < NBIG) {
        rvq_body<128>(X, CB, Y, smem, (long long)blockIdx.x * 128);
    } else {
        rvq_body<64>(X, CB, Y, smem,
                     (long long)NBIG * 128 + (long long)(blockIdx.x - NBIG) * 64);
    }
}

// ---------------------------------------------------------------------------
__global__ void finalize_kernel(float* __restrict__ Y, int out_size) {
    __shared__ double sd[1024];
    int tid = threadIdx.x;
    sd[tid] = (tid < GRID) ? g_commitPartial[tid] : 0.0;
    for (int s = 512; s > 0; s >>= 1) {
        __syncthreads();
        if (tid < s) sd[tid] += sd[tid + s];
    }
    if (tid == 0) {
        double mean = sd[0] / (double)((long long)NTOK * DDIM);
        float commit = (float)(0.25 * mean);
        long long numel = (long long)NTOK * DDIM;
        for (long long j = numel; j < (long long)out_size; j++) Y[j] = commit;
    }
}

extern "C" void kernel_launch(void* const* d_in, const int* in_sizes, int n_in,
                              void* d_out, int out_size) {
    const float* X  = (const float*)d_in[0];
    const float* CB = (const float*)d_in[1];
    float* Y = (float*)d_out;

    cudaFuncSetAttribute(rvq_mma, cudaFuncAttributeMaxDynamicSharedMemorySize,
                         SMEM_TOTAL);

    prep_all<<<512, 256>>>(CB);
    rvq_mma<<<GRID, THREADS, SMEM_TOTAL>>>(X, CB, Y);
    finalize_kernel<<<1, 1024>>>(Y, out_size);
}

// round 15
// speedup vs baseline: 1.2446x; 1.0318x over previous
#include <cuda_runtime.h>
#include <cuda_bf16.h>
#include <cstdint>

// Problem constants
#define NTOK    65536
#define DDIM    256
#define KCODES  1024
#define MLVL    4
#define THREADS 512
#define RS      260            // fp32 residual row stride (floats)
#define MARGIN  4e-4f
// Mixed tiling: 432 big tiles (128 tok) + 160 small tiles (64 tok) = 592 = 4*148
#define NBIG    432
#define NSMALL  160
#define GRID    (NBIG + NSMALL)

// SMEM byte offsets (dynamic smem, total 228880)
#define OFF_RSH    0            // 133120: [128][260] fp32 residual
#define OFF_AFRAG  133120       // 65536:  A fragments [mt][ks16][lane32] uint4
#define OFF_BBUF   198656       // 24576:  3 x 8KB B slices (ring)
// Overlays inside BBUF (dead while ring unused; barrier-separated):
#define OFF_HTD    198656       // float4 topDist[seg][tok] (8192)
#define OFF_HTI    206848       // int4   topIdx [seg][tok] (8192)
#define OFF_CIDX   215040       // int4   candIdx[128]      (2048)
#define OFF_REDD   217088       // double redD[512]         (4096)
#define OFF_E2     223232       // 4096
#define OFF_R2     227328       // 512
#define OFF_BEST   227840       // 512
#define OFF_CTOK   228352       // 512
#define OFF_CCNT   228864       // 16
#define SMEM_TOTAL 228880

__device__ float  g_e2[MLVL * KCODES];
__device__ double g_commitPartial[GRID];
// B fragments: [lvl][slice(64)][512 x uint4]  (slice = nc*8 + kb, 8KB each)
__device__ uint4  g_cbfrag[MLVL * 64 * 512];

static __device__ __forceinline__ uint32_t pkbf(float a, float b) {
    __nv_bfloat162 h = __floats2bfloat162_rn(a, b);
    return *reinterpret_cast<uint32_t*>(&h);
}
static __device__ __forceinline__ void mma16816(float* c, const uint4& A,
                                                uint32_t b0, uint32_t b1) {
    asm volatile(
        "mma.sync.aligned.m16n8k16.row.col.f32.bf16.bf16.f32 "
        "{%0,%1,%2,%3}, {%4,%5,%6,%7}, {%8,%9}, {%0,%1,%2,%3};"
        : "+f"(c[0]), "+f"(c[1]), "+f"(c[2]), "+f"(c[3])
        : "r"(A.x), "r"(A.y), "r"(A.z), "r"(A.w), "r"(b0), "r"(b1));
}
static __device__ __forceinline__ void cpasync16(void* dst, const void* src) {
    uint32_t d = (uint32_t)__cvta_generic_to_shared(dst);
    asm volatile("cp.async.cg.shared.global [%0], [%1], 16;" :: "r"(d), "l"(src));
}
#define CP_COMMIT() asm volatile("cp.async.commit_group;")
#define CP_WAIT(n)  asm volatile("cp.async.wait_group %0;" :: "n"(n))

// ---------------------------------------------------------------------------
// Merged prep: per-thread codebook fragment pack + per-warp e2 row.
// ---------------------------------------------------------------------------
__global__ void prep_all(const float* __restrict__ cb) {
    int id = blockIdx.x * blockDim.x + threadIdx.x;
    if (id < MLVL * 64 * 512) {
        int u    = id & 511;
        int half = u >> 8;
        int nt   = (u >> 5) & 7;
        int lane = u & 31;
        int s    = (id >> 9) & 63;
        int lvl  = id >> 15;
        int nc = s >> 3, kb = s & 7;
        int n  = nc * 128 + half * 64 + nt * 8 + (lane >> 2);
        int k0 = kb * 32 + (lane & 3) * 2;
        const float* row = cb + ((size_t)lvl * KCODES + n) * DDIM;
        uint4 v;
        v.x = pkbf(row[k0],      row[k0 + 1]);
        v.y = pkbf(row[k0 + 8],  row[k0 + 9]);
        v.z = pkbf(row[k0 + 16], row[k0 + 17]);
        v.w = pkbf(row[k0 + 24], row[k0 + 25]);
        g_cbfrag[id] = v;
    }
    int warp = id >> 5;
    int lane = id & 31;
    if (warp < MLVL * KCODES) {
        const float* row = cb + (size_t)warp * DDIM;
        double s = 0.0;
#pragma unroll
        for (int m = 0; m < DDIM / 32; m++) {
            float v = row[lane + 32 * m];
            s += (double)v * (double)v;
        }
#pragma unroll
        for (int off = 16; off; off >>= 1) s += __shfl_xor_sync(0xffffffffu, s, off);
        if (lane == 0) g_e2[warp] = (float)s;
    }
}

// ---------------------------------------------------------------------------
struct Top3 { float d0, d1, d2; int i0, i1, i2; };
static __device__ __forceinline__ void t3_insert(Top3& T, float d, int idx) {
    if (d < T.d2) {
        if (d < T.d1) {
            T.d2 = T.d1; T.i2 = T.i1;
            if (d < T.d0) { T.d1 = T.d0; T.i1 = T.i0; T.d0 = d; T.i0 = idx; }
            else          { T.d1 = d;    T.i1 = idx; }
        } else { T.d2 = d; T.i2 = idx; }
    }
}
static __device__ __forceinline__ void t4_insert(float* d, int* i, float nd, int ni) {
    bool l3 = (nd < d[3]) || (nd == d[3] && ni < i[3]);
    if (!l3) return;
    bool l2 = (nd < d[2]) || (nd == d[2] && ni < i[2]);
    bool l1 = (nd < d[1]) || (nd == d[1] && ni < i[1]);
    bool l0 = (nd < d[0]) || (nd == d[0] && ni < i[0]);
    if (l0)      { d[3]=d[2]; i[3]=i[2]; d[2]=d[1]; i[2]=i[1]; d[1]=d[0]; i[1]=i[0]; d[0]=nd; i[0]=ni; }
    else if (l1) { d[3]=d[2]; i[3]=i[2]; d[2]=d[1]; i[2]=i[1]; d[1]=nd; i[1]=ni; }
    else if (l2) { d[3]=d[2]; i[3]=i[2]; d[2]=nd; i[2]=ni; }
    else         { d[3]=nd; i[3]=ni; }
}

// ---------------------------------------------------------------------------
// Templated body: fully compile-time tile geometry (round-5 chassis).
//   TMLOC=128: 8 M-warps x 2 N-segments, warp tile 16 tok x 64 codes
//   TMLOC=64 : 4 M-warps x 4 N-segments, warp tile 16 tok x 32 codes
// ---------------------------------------------------------------------------
template<int TMLOC>
static __device__ __forceinline__ void rvq_body(
    const float* __restrict__ X, const float* __restrict__ CB,
    float* __restrict__ Y, char* smem, long long tokenBase) {
    constexpr int NWM  = TMLOC / 16;    // warps along M (8 or 4)
    constexpr int NSEG = 16 / NWM;      // N segments (2 or 4)
    constexpr int NTT  = 16 / NSEG;     // ntiles per warp (8 or 4)
    constexpr int CSEG = 128 / NSEG;    // codes per segment (64 or 32)

    float*  Rsh     = (float*)(smem + OFF_RSH);
    uint4*  Af      = (uint4*)(smem + OFF_AFRAG);
    uint4*  Bb      = (uint4*)(smem + OFF_BBUF);
    float4* htd     = (float4*)(smem + OFF_HTD);
    int4*   hti     = (int4*)(smem + OFF_HTI);
    int4*   candIdx = (int4*)(smem + OFF_CIDX);
    double* redD    = (double*)(smem + OFF_REDD);
    float*  e2Sh    = (float*)(smem + OFF_E2);
    float*  r2Sh    = (float*)(smem + OFF_R2);
    int*    bestI   = (int*)(smem + OFF_BEST);
    int*    candTok = (int*)(smem + OFF_CTOK);
    int*    candCnt = (int*)(smem + OFF_CCNT);

    const int tid  = threadIdx.x;
    const int wid  = tid >> 5;
    const int lane = tid & 31;
    const int wm   = wid % NWM;
    const int wn   = wid / NWM;
    const int bOff = (CSEG == 64) ? wn * 256 : ((wn >> 1) * 256 + (wn & 1) * 128);
    const int g    = lane >> 2;
    const int tg2  = (lane & 3) * 2;
    const float* Xblk = X + tokenBase * DDIM;
    const float INF = __int_as_float(0x7f800000);

    // ---- load X tile -----------------------------------------------------
    for (int idx = tid; idx < TMLOC * (DDIM / 4); idx += THREADS) {
        int t = idx >> 6, dq = (idx & 63) << 2;
        *(float4*)(Rsh + t * RS + dq) = *(const float4*)(Xblk + (long long)t * DDIM + dq);
    }
    __syncthreads();

    // ---- initial r2 (fp64 -> fp32) ---------------------------------------
    {
        int t = tid >> 2, h = tid & 3;
        if (t < TMLOC) {
            const float* rr = Rsh + t * RS + h * 64;
            double s = 0.0;
            for (int k = 0; k < 64; k++) { float f = rr[k]; s += (double)f * f; }
            redD[tid] = s;
        }
        __syncthreads();
        if (t < TMLOC && !h)
            r2Sh[t] = (float)(redD[tid] + redD[tid + 1] + redD[tid + 2] + redD[tid + 3]);
    }
    __syncthreads();

    double commitAcc = 0.0;

    for (int lvl = 0; lvl < MLVL; lvl++) {
        // ---- level setup: e2, candCnt, A fragments (bf16) ----------------
        if (tid == 0) *candCnt = 0;
        for (int i = tid; i < KCODES; i += THREADS) e2Sh[i] = g_e2[lvl * KCODES + i];
        for (int idx = tid; idx < TMLOC * 32; idx += THREADS) {
            int mt = idx >> 9, ks = (idx >> 5) & 15, ln = idx & 31;
            int m0 = mt * 16 + (ln >> 2);
            int k0 = ks * 16 + (ln & 3) * 2;
            const float* ra = Rsh + m0 * RS;
            const float* rb = Rsh + (m0 + 8) * RS;
            uint4 v;
            v.x = pkbf(ra[k0],     ra[k0 + 1]);
            v.y = pkbf(rb[k0],     rb[k0 + 1]);
            v.z = pkbf(ra[k0 + 8], ra[k0 + 9]);
            v.w = pkbf(rb[k0 + 8], rb[k0 + 9]);
            Af[idx] = v;
        }
        __syncthreads();   // Af ready; ring overlays dead below

        const float r2a = r2Sh[wm * 16 + g];
        const float r2b = r2Sh[wm * 16 + g + 8];

        Top3 T[2];
#pragma unroll
        for (int q = 0; q < 2; q++) { T[q].d0 = T[q].d1 = T[q].d2 = INF; T[q].i0 = T[q].i1 = T[q].i2 = 0x7fffffff; }

        const uint4* gb = g_cbfrag + (size_t)lvl * 64 * 512;

        // ---- prologue: prefetch stages 0,1 (one 16B per thread each) -----
        cpasync16(Bb + 0 * 512 + tid, gb + 0 * 512 + tid);
        CP_COMMIT();
        cpasync16(Bb + 1 * 512 + tid, gb + 1 * 512 + tid);
        CP_COMMIT();

        float acc[NTT][4];
        int cur = 0;

        for (int sl = 0; sl < 64; sl++) {
            const int kb = sl & 7;
            CP_WAIT(1);        // stage sl landed
            __syncthreads();   // visible to all; all done with buf (sl-1)%3
            if (sl + 2 < 64) {
                int nb = cur == 0 ? 2 : cur - 1;   // (sl+2)%3
                cpasync16(Bb + nb * 512 + tid, gb + (size_t)(sl + 2) * 512 + tid);
            }
            CP_COMMIT();       // unconditional: uniform group indexing

            if (kb == 0) {
#pragma unroll
                for (int nt = 0; nt < NTT; nt++)
#pragma unroll
                    for (int c = 0; c < 4; c++) acc[nt][c] = 0.f;
            }

            uint4 A0 = Af[(wm * 16 + kb * 2 + 0) * 32 + lane];
            uint4 A1 = Af[(wm * 16 + kb * 2 + 1) * 32 + lane];
            const uint4* Bp = Bb + cur * 512 + bOff + lane;
            uint4 Bv[NTT];
#pragma unroll
            for (int nt = 0; nt < NTT; nt++) Bv[nt] = Bp[nt * 32];
#pragma unroll
            for (int nt = 0; nt < NTT; nt++) mma16816(acc[nt], A0, Bv[nt].x, Bv[nt].y);
#pragma unroll
            for (int nt = 0; nt < NTT; nt++) mma16816(acc[nt], A1, Bv[nt].z, Bv[nt].w);

            // ---- per-chunk epilogue: dist + top-3 streaming --------------
            if (kb == 7) {
                const int nc = sl >> 3;
#pragma unroll
                for (int nt = 0; nt < NTT; nt++) {
                    int nbase = nc * 128 + wn * CSEG + nt * 8 + tg2;
                    float2 e2p = *(const float2*)&e2Sh[nbase];
                    t3_insert(T[0], fmaf(-2.f, acc[nt][0], r2a + e2p.x), nbase);
                    t3_insert(T[0], fmaf(-2.f, acc[nt][1], r2a + e2p.y), nbase + 1);
                    t3_insert(T[1], fmaf(-2.f, acc[nt][2], r2b + e2p.x), nbase);
                    t3_insert(T[1], fmaf(-2.f, acc[nt][3], r2b + e2p.y), nbase + 1);
                }
            }
            cur = cur == 2 ? 0 : cur + 1;
        } // slices

        __syncthreads();   // compute done before htd/hti overlay ring

        // ---- quad merge, publish per-(segment,token) top-4 to SMEM -------
#pragma unroll
        for (int q = 0; q < 2; q++) {
            float md[4] = { T[q].d0, T[q].d1, T[q].d2, INF };
            int   mi[4] = { T[q].i0, T[q].i1, T[q].i2, 0x7fffffff };
#pragma unroll
            for (int off = 1; off <= 2; off <<= 1) {
                float od[4]; int oi[4];
#pragma unroll
                for (int j = 0; j < 4; j++) {
                    od[j] = __shfl_xor_sync(0xffffffffu, md[j], off);
                    oi[j] = __shfl_xor_sync(0xffffffffu, mi[j], off);
                }
#pragma unroll
                for (int j = 0; j < 4; j++) t4_insert(md, mi, od[j], oi[j]);
            }
            if ((lane & 3) == 0) {
                int tok = wm * 16 + g + q * 8;
                htd[wn * TMLOC + tok] = make_float4(md[0], md[1], md[2], md[3]);
                hti[wn * TMLOC + tok] = make_int4(mi[0], mi[1], mi[2], mi[3]);
            }
        }
        __syncthreads();

        // ---- cross-segment merge + decision (one thread per token) -------
        if (tid < TMLOC) {
            float4 d0 = htd[tid];  int4 i0 = hti[tid];
            float md[4] = { d0.x, d0.y, d0.z, d0.w };
            int   mi[4] = { i0.x, i0.y, i0.z, i0.w };
#pragma unroll
            for (int h = 1; h < NSEG; h++) {
                float4 dh = htd[h * TMLOC + tid];  int4 ih = hti[h * TMLOC + tid];
                t4_insert(md, mi, dh.x, ih.x);
                t4_insert(md, mi, dh.y, ih.y);
                t4_insert(md, mi, dh.z, ih.z);
                t4_insert(md, mi, dh.w, ih.w);
            }
            if (md[1] >= md[0] + MARGIN) {
                bestI[tid] = mi[0];
            } else {
                int p = atomicAdd(candCnt, 1);
                candTok[p] = tid;
                candIdx[tid] = make_int4(mi[0], mi[1], mi[2], mi[3]);
            }
        }
        __syncthreads();

        // ---- rescue: exact fp32 dots for flagged tokens (warp per entry) -
        {
            int cnt = *candCnt;
            for (int e = wid; e < cnt; e += 16) {
                int tok = candTok[e];
                int4 cs = candIdx[tok];
                float r2t = r2Sh[tok];
                const float* rrow = Rsh + tok * RS + lane * 8;
                float bd = INF; int bi = 0x7fffffff;
#pragma unroll
                for (int j = 0; j < 4; j++) {
                    int idx = (&cs.x)[j];
                    const float* crow = CB + ((size_t)lvl * KCODES + idx) * DDIM + lane * 8;
                    float p = 0.f;
#pragma unroll
                    for (int u = 0; u < 8; u++) p = fmaf(rrow[u], crow[u], p);
#pragma unroll
                    for (int o = 16; o; o >>= 1) p += __shfl_xor_sync(0xffffffffu, p, o);
                    float dd = fmaf(-2.f, p, r2t + e2Sh[idx]);
                    if (dd < bd || (dd == bd && idx < bi)) { bd = dd; bi = idx; }
                }
                if (lane == 0) bestI[tok] = bi;
            }
        }
        __syncthreads();

        // ---- residual update + new r2 + commit (4 threads / token) -------
        {
            int t = tid >> 2, h = tid & 3;
            if (t < TMLOC) {
                int b = bestI[t];
                const float* qv = CB + ((size_t)lvl * KCODES + b) * DDIM + h * 64;
                float* rr = Rsh + t * RS + h * 64;
                double ss = 0.0;
                for (int k = 0; k < 64; k += 4) {
                    float4 q4 = *(const float4*)(qv + k);
                    float n0 = rr[k]     - q4.x;
                    float n1 = rr[k + 1] - q4.y;
                    float n2 = rr[k + 2] - q4.z;
                    float n3 = rr[k + 3] - q4.w;
                    rr[k] = n0; rr[k + 1] = n1; rr[k + 2] = n2; rr[k + 3] = n3;
                    ss += (double)n0 * n0 + (double)n1 * n1
                        + (double)n2 * n2 + (double)n3 * n3;
                }
                redD[tid] = ss;
                commitAcc += ss;
            }
            __syncthreads();
            if (t < TMLOC && !h)
                r2Sh[t] = (float)(redD[tid] + redD[tid + 1] + redD[tid + 2] + redD[tid + 3]);
        }
        __syncthreads();
    } // levels

    // ---- y = x - r_final ---------------------------------------------------
    for (int idx = tid; idx < TMLOC * (DDIM / 4); idx += THREADS) {
        int t = idx >> 6, dq = (idx & 63) << 2;
        float4 xv = *(const float4*)(Xblk + (long long)t * DDIM + dq);
        const float* rr = Rsh + t * RS + dq;
        float4 y;
        y.x = xv.x - rr[0]; y.y = xv.y - rr[1];
        y.z = xv.z - rr[2]; y.w = xv.w - rr[3];
        *(float4*)(Y + (tokenBase + t) * DDIM + dq) = y;
    }

    // ---- deterministic per-block commit partial ----------------------------
    redD[tid] = commitAcc;
    for (int s = THREADS / 2; s > 0; s >>= 1) {
        __syncthreads();
        if (tid < s) redD[tid] += redD[tid + s];
    }
    if (tid == 0) g_commitPartial[blockIdx.x] = redD[0];
}

// ---------------------------------------------------------------------------
__global__ __launch_bounds__(THREADS, 1)
void rvq_mma(const float* __restrict__ X, const float* __restrict__ CB,
             float* __restrict__ Y) {
    extern __shared__ char smem[];
    if (blockIdx.x < NBIG) {
        rvq_body<128>(X, CB, Y, smem, (long long)blockIdx.x * 128);
    } else {
        rvq_body<64>(X, CB, Y, smem,
                     (long long)NBIG * 128 + (long long)(blockIdx.x - NBIG) * 64);
    }
}

// ---------------------------------------------------------------------------
__global__ void finalize_kernel(float* __restrict__ Y, int out_size) {
    __shared__ double sd[1024];
    int tid = threadIdx.x;
    sd[tid] = (tid < GRID) ? g_commitPartial[tid] : 0.0;
    for (int s = 512; s > 0; s >>= 1) {
        __syncthreads();
        if (tid < s) sd[tid] += sd[tid + s];
    }
    if (tid == 0) {
        double mean = sd[0] / (double)((long long)NTOK * DDIM);
        float commit = (float)(0.25 * mean);
        long long numel = (long long)NTOK * DDIM;
        for (long long j = numel; j < (long long)out_size; j++) Y[j] = commit;
    }
}

extern "C" void kernel_launch(void* const* d_in, const int* in_sizes, int n_in,
                              void* d_out, int out_size) {
    const float* X  = (const float*)d_in[0];
    const float* CB = (const float*)d_in[1];
    float* Y = (float*)d_out;

    cudaFuncSetAttribute(rvq_mma, cudaFuncAttributeMaxDynamicSharedMemorySize,
                         SMEM_TOTAL);

    prep_all<<<512, 256>>>(CB);
    rvq_mma<<<GRID, THREADS, SMEM_TOTAL>>>(X, CB, Y);
    finalize_kernel<<<1, 1024>>>(Y, out_size);
}

// round 16
// speedup vs baseline: 1.2564x; 1.0095x over previous
#include <cuda_runtime.h>
#include <cuda_bf16.h>
#include <cstdint>

// Problem constants
#define NTOK    65536
#define DDIM    256
#define KCODES  1024
#define MLVL    4
#define THREADS 512
#define RS      260            // fp32 residual row stride (floats)
#define MARGIN  4e-4f
// Mixed tiling: 432 big tiles (128 tok) + 160 small tiles (64 tok) = 592 = 4*148
#define NBIG    432
#define NSMALL  160
#define GRID    (NBIG + NSMALL)

// SMEM byte offsets (dynamic smem, total 228880)
#define OFF_RSH    0            // 133120: [128][260] fp32 residual
                                 //   (small path uses rows 0..63 = 66560 B;
                                 //    its 6-stage ring lives at +66560)
#define OFF_RING64 66560        // small-path ring: 6 x 8KB = 49152 (<133120)
#define OFF_AFRAG  133120       // 65536:  A fragments [mt][ks16][lane32] uint4
#define OFF_BBUF   198656       // 24576:  3 x 8KB B slices (big-path ring)
// Overlays inside BBUF (dead while big ring unused; barrier-separated).
// Small path's ring is at OFF_RING64, so these overlays are trivially safe there.
#define OFF_HTD    198656       // float4 topDist[seg][tok] (8192)
#define OFF_HTI    206848       // int4   topIdx [seg][tok] (8192)
#define OFF_CIDX   215040       // int4   candIdx[128]      (2048)
#define OFF_REDD   217088       // double redD[512]         (4096)
#define OFF_E2     223232       // 4096
#define OFF_R2     227328       // 512
#define OFF_BEST   227840       // 512
#define OFF_CTOK   228352       // 512
#define OFF_CCNT   228864       // 16
#define SMEM_TOTAL 228880

__device__ float  g_e2[MLVL * KCODES];
__device__ double g_commitPartial[GRID];
// B fragments: [lvl][slice(64)][512 x uint4]  (slice = nc*8 + kb, 8KB each)
__device__ uint4  g_cbfrag[MLVL * 64 * 512];

static __device__ __forceinline__ uint32_t pkbf(float a, float b) {
    __nv_bfloat162 h = __floats2bfloat162_rn(a, b);
    return *reinterpret_cast<uint32_t*>(&h);
}
static __device__ __forceinline__ void mma16816(float* c, const uint4& A,
                                                uint32_t b0, uint32_t b1) {
    asm volatile(
        "mma.sync.aligned.m16n8k16.row.col.f32.bf16.bf16.f32 "
        "{%0,%1,%2,%3}, {%4,%5,%6,%7}, {%8,%9}, {%0,%1,%2,%3};"
        : "+f"(c[0]), "+f"(c[1]), "+f"(c[2]), "+f"(c[3])
        : "r"(A.x), "r"(A.y), "r"(A.z), "r"(A.w), "r"(b0), "r"(b1));
}
static __device__ __forceinline__ void cpasync16(void* dst, const void* src) {
    uint32_t d = (uint32_t)__cvta_generic_to_shared(dst);
    asm volatile("cp.async.cg.shared.global [%0], [%1], 16;" :: "r"(d), "l"(src));
}
#define CP_COMMIT() asm volatile("cp.async.commit_group;")
#define CP_WAIT(n)  asm volatile("cp.async.wait_group %0;" :: "n"(n))

// ---------------------------------------------------------------------------
// Merged prep: per-thread codebook fragment pack + per-warp e2 row.
// ---------------------------------------------------------------------------
__global__ void prep_all(const float* __restrict__ cb) {
    int id = blockIdx.x * blockDim.x + threadIdx.x;
    if (id < MLVL * 64 * 512) {
        int u    = id & 511;
        int half = u >> 8;
        int nt   = (u >> 5) & 7;
        int lane = u & 31;
        int s    = (id >> 9) & 63;
        int lvl  = id >> 15;
        int nc = s >> 3, kb = s & 7;
        int n  = nc * 128 + half * 64 + nt * 8 + (lane >> 2);
        int k0 = kb * 32 + (lane & 3) * 2;
        const float* row = cb + ((size_t)lvl * KCODES + n) * DDIM;
        uint4 v;
        v.x = pkbf(row[k0],      row[k0 + 1]);
        v.y = pkbf(row[k0 + 8],  row[k0 + 9]);
        v.z = pkbf(row[k0 + 16], row[k0 + 17]);
        v.w = pkbf(row[k0 + 24], row[k0 + 25]);
        g_cbfrag[id] = v;
    }
    int warp = id >> 5;
    int lane = id & 31;
    if (warp < MLVL * KCODES) {
        const float* row = cb + (size_t)warp * DDIM;
        double s = 0.0;
#pragma unroll
        for (int m = 0; m < DDIM / 32; m++) {
            float v = row[lane + 32 * m];
            s += (double)v * (double)v;
        }
#pragma unroll
        for (int off = 16; off; off >>= 1) s += __shfl_xor_sync(0xffffffffu, s, off);
        if (lane == 0) g_e2[warp] = (float)s;
    }
}

// ---------------------------------------------------------------------------
struct Top3 { float d0, d1, d2; int i0, i1, i2; };
static __device__ __forceinline__ void t3_insert(Top3& T, float d, int idx) {
    if (d < T.d2) {
        if (d < T.d1) {
            T.d2 = T.d1; T.i2 = T.i1;
            if (d < T.d0) { T.d1 = T.d0; T.i1 = T.i0; T.d0 = d; T.i0 = idx; }
            else          { T.d1 = d;    T.i1 = idx; }
        } else { T.d2 = d; T.i2 = idx; }
    }
}
static __device__ __forceinline__ void t4_insert(float* d, int* i, float nd, int ni) {
    bool l3 = (nd < d[3]) || (nd == d[3] && ni < i[3]);
    if (!l3) return;
    bool l2 = (nd < d[2]) || (nd == d[2] && ni < i[2]);
    bool l1 = (nd < d[1]) || (nd == d[1] && ni < i[1]);
    bool l0 = (nd < d[0]) || (nd == d[0] && ni < i[0]);
    if (l0)      { d[3]=d[2]; i[3]=i[2]; d[2]=d[1]; i[2]=i[1]; d[1]=d[0]; i[1]=i[0]; d[0]=nd; i[0]=ni; }
    else if (l1) { d[3]=d[2]; i[3]=i[2]; d[2]=d[1]; i[2]=i[1]; d[1]=nd; i[1]=ni; }
    else if (l2) { d[3]=d[2]; i[3]=i[2]; d[2]=nd; i[2]=ni; }
    else         { d[3]=nd; i[3]=ni; }
}

// ---------------------------------------------------------------------------
// Templated body.
//   TMLOC=128: 8 M-warps x 2 N-segs, 3-stage ring at OFF_BBUF, 1 slice/iter
//              (compiles to exactly the proven round-12 mainloop)
//   TMLOC=64 : 4 M-warps x 4 N-segs, 6-stage ring at OFF_RING64, 2 slices/iter
//              (halves per-slice fixed costs: 32 iterations, 16 HMMA/warp each)
// ---------------------------------------------------------------------------
template<int TMLOC>
static __device__ __forceinline__ void rvq_body(
    const float* __restrict__ X, const float* __restrict__ CB,
    float* __restrict__ Y, char* smem, long long tokenBase) {
    constexpr int NWM  = TMLOC / 16;    // warps along M (8 or 4)
    constexpr int NSEG = 16 / NWM;      // N segments (2 or 4)
    constexpr int NTT  = 16 / NSEG;     // ntiles per warp (8 or 4)
    constexpr int CSEG = 128 / NSEG;    // codes per segment (64 or 32)
    constexpr int SPI  = (TMLOC == 64) ? 2 : 1;   // slices per iteration
    constexpr int NIT  = 64 / SPI;
    constexpr int RINGOFF = (TMLOC == 64) ? OFF_RING64 : OFF_BBUF;

    float*  Rsh     = (float*)(smem + OFF_RSH);
    uint4*  Af      = (uint4*)(smem + OFF_AFRAG);
    uint4*  Ring    = (uint4*)(smem + RINGOFF);
    float4* htd     = (float4*)(smem + OFF_HTD);
    int4*   hti     = (int4*)(smem + OFF_HTI);
    int4*   candIdx = (int4*)(smem + OFF_CIDX);
    double* redD    = (double*)(smem + OFF_REDD);
    float*  e2Sh    = (float*)(smem + OFF_E2);
    float*  r2Sh    = (float*)(smem + OFF_R2);
    int*    bestI   = (int*)(smem + OFF_BEST);
    int*    candTok = (int*)(smem + OFF_CTOK);
    int*    candCnt = (int*)(smem + OFF_CCNT);

    const int tid  = threadIdx.x;
    const int wid  = tid >> 5;
    const int lane = tid & 31;
    const int wm   = wid % NWM;
    const int wn   = wid / NWM;
    const int bOff = (CSEG == 64) ? wn * 256 : ((wn >> 1) * 256 + (wn & 1) * 128);
    const int g    = lane >> 2;
    const int tg2  = (lane & 3) * 2;
    const float* Xblk = X + tokenBase * DDIM;
    const float INF = __int_as_float(0x7f800000);

    // ---- load X tile -----------------------------------------------------
    for (int idx = tid; idx < TMLOC * (DDIM / 4); idx += THREADS) {
        int t = idx >> 6, dq = (idx & 63) << 2;
        *(float4*)(Rsh + t * RS + dq) = *(const float4*)(Xblk + (long long)t * DDIM + dq);
    }
    __syncthreads();

    // ---- initial r2 (fp64 -> fp32) ---------------------------------------
    {
        int t = tid >> 2, h = tid & 3;
        if (t < TMLOC) {
            const float* rr = Rsh + t * RS + h * 64;
            double s = 0.0;
            for (int k = 0; k < 64; k++) { float f = rr[k]; s += (double)f * f; }
            redD[tid] = s;
        }
        __syncthreads();
        if (t < TMLOC && !h)
            r2Sh[t] = (float)(redD[tid] + redD[tid + 1] + redD[tid + 2] + redD[tid + 3]);
    }
    __syncthreads();

    double commitAcc = 0.0;

    for (int lvl = 0; lvl < MLVL; lvl++) {
        // ---- level setup: e2, candCnt, A fragments (bf16) ----------------
        if (tid == 0) *candCnt = 0;
        for (int i = tid; i < KCODES; i += THREADS) e2Sh[i] = g_e2[lvl * KCODES + i];
        for (int idx = tid; idx < TMLOC * 32; idx += THREADS) {
            int mt = idx >> 9, ks = (idx >> 5) & 15, ln = idx & 31;
            int m0 = mt * 16 + (ln >> 2);
            int k0 = ks * 16 + (ln & 3) * 2;
            const float* ra = Rsh + m0 * RS;
            const float* rb = Rsh + (m0 + 8) * RS;
            uint4 v;
            v.x = pkbf(ra[k0],     ra[k0 + 1]);
            v.y = pkbf(rb[k0],     rb[k0 + 1]);
            v.z = pkbf(ra[k0 + 8], ra[k0 + 9]);
            v.w = pkbf(rb[k0 + 8], rb[k0 + 9]);
            Af[idx] = v;
        }
        __syncthreads();   // Af ready; ring overlays dead below

        const float r2a = r2Sh[wm * 16 + g];
        const float r2b = r2Sh[wm * 16 + g + 8];

        Top3 T[2];
#pragma unroll
        for (int q = 0; q < 2; q++) { T[q].d0 = T[q].d1 = T[q].d2 = INF; T[q].i0 = T[q].i1 = T[q].i2 = 0x7fffffff; }

        const uint4* gb = g_cbfrag + (size_t)lvl * 64 * 512;

        // ---- prologue: prefetch pair-groups 0,1 (SPI slices each) --------
#pragma unroll
        for (int p = 0; p < 2; p++) {
#pragma unroll
            for (int j = 0; j < SPI; j++)
                cpasync16(Ring + (p * SPI + j) * 512 + tid,
                          gb + (size_t)(p * SPI + j) * 512 + tid);
            CP_COMMIT();
        }

        float acc[NTT][4];
        int cur = 0;

        for (int it = 0; it < NIT; it++) {
            CP_WAIT(1);        // group 'it' landed
            __syncthreads();   // visible to all; all done with group (it-1)%3
            if (it + 2 < NIT) {
                int nb = cur == 0 ? 2 : cur - 1;   // (it+2)%3
#pragma unroll
                for (int j = 0; j < SPI; j++)
                    cpasync16(Ring + (nb * SPI + j) * 512 + tid,
                              gb + (size_t)((it + 2) * SPI + j) * 512 + tid);
            }
            CP_COMMIT();       // unconditional: uniform group indexing

#pragma unroll
            for (int j = 0; j < SPI; j++) {
                const int sl = it * SPI + j;
                const int kb = sl & 7;

                if (kb == 0) {
#pragma unroll
                    for (int nt = 0; nt < NTT; nt++)
#pragma unroll
                        for (int c = 0; c < 4; c++) acc[nt][c] = 0.f;
                }

                uint4 A0 = Af[(wm * 16 + kb * 2 + 0) * 32 + lane];
                uint4 A1 = Af[(wm * 16 + kb * 2 + 1) * 32 + lane];
                const uint4* Bp = Ring + (cur * SPI + j) * 512 + bOff + lane;
                uint4 Bv[NTT];
#pragma unroll
                for (int nt = 0; nt < NTT; nt++) Bv[nt] = Bp[nt * 32];
#pragma unroll
                for (int nt = 0; nt < NTT; nt++) mma16816(acc[nt], A0, Bv[nt].x, Bv[nt].y);
#pragma unroll
                for (int nt = 0; nt < NTT; nt++) mma16816(acc[nt], A1, Bv[nt].z, Bv[nt].w);

                // ---- per-chunk epilogue: dist + top-3 streaming ----------
                if (kb == 7) {
                    const int nc = sl >> 3;
#pragma unroll
                    for (int nt = 0; nt < NTT; nt++) {
                        int nbase = nc * 128 + wn * CSEG + nt * 8 + tg2;
                        float2 e2p = *(const float2*)&e2Sh[nbase];
                        t3_insert(T[0], fmaf(-2.f, acc[nt][0], r2a + e2p.x), nbase);
                        t3_insert(T[0], fmaf(-2.f, acc[nt][1], r2a + e2p.y), nbase + 1);
                        t3_insert(T[1], fmaf(-2.f, acc[nt][2], r2b + e2p.x), nbase);
                        t3_insert(T[1], fmaf(-2.f, acc[nt][3], r2b + e2p.y), nbase + 1);
                    }
                }
            }
            cur = cur == 2 ? 0 : cur + 1;
        } // iterations

        __syncthreads();   // compute done before htd/hti overlay (big path)

        // ---- quad merge, publish per-(segment,token) top-4 to SMEM -------
#pragma unroll
        for (int q = 0; q < 2; q++) {
            float md[4] = { T[q].d0, T[q].d1, T[q].d2, INF };
            int   mi[4] = { T[q].i0, T[q].i1, T[q].i2, 0x7fffffff };
#pragma unroll
            for (int off = 1; off <= 2; off <<= 1) {
                float od[4]; int oi[4];
#pragma unroll
                for (int j = 0; j < 4; j++) {
                    od[j] = __shfl_xor_sync(0xffffffffu, md[j], off);
                    oi[j] = __shfl_xor_sync(0xffffffffu, mi[j], off);
                }
#pragma unroll
                for (int j = 0; j < 4; j++) t4_insert(md, mi, od[j], oi[j]);
            }
            if ((lane & 3) == 0) {
                int tok = wm * 16 + g + q * 8;
                htd[wn * TMLOC + tok] = make_float4(md[0], md[1], md[2], md[3]);
                hti[wn * TMLOC + tok] = make_int4(mi[0], mi[1], mi[2], mi[3]);
            }
        }
        __syncthreads();

        // ---- cross-segment merge + decision (one thread per token) -------
        if (tid < TMLOC) {
            float4 d0 = htd[tid];  int4 i0 = hti[tid];
            float md[4] = { d0.x, d0.y, d0.z, d0.w };
            int   mi[4] = { i0.x, i0.y, i0.z, i0.w };
#pragma unroll
            for (int h = 1; h < NSEG; h++) {
                float4 dh = htd[h * TMLOC + tid];  int4 ih = hti[h * TMLOC + tid];
                t4_insert(md, mi, dh.x, ih.x);
                t4_insert(md, mi, dh.y, ih.y);
                t4_insert(md, mi, dh.z, ih.z);
                t4_insert(md, mi, dh.w, ih.w);
            }
            if (md[1] >= md[0] + MARGIN) {
                bestI[tid] = mi[0];
            } else {
                int p = atomicAdd(candCnt, 1);
                candTok[p] = tid;
                candIdx[tid] = make_int4(mi[0], mi[1], mi[2], mi[3]);
            }
        }
        __syncthreads();

        // ---- rescue: exact fp32 dots for flagged tokens (warp per entry) -
        {
            int cnt = *candCnt;
            for (int e = wid; e < cnt; e += 16) {
                int tok = candTok[e];
                int4 cs = candIdx[tok];
                float r2t = r2Sh[tok];
                const float* rrow = Rsh + tok * RS + lane * 8;
                float bd = INF; int bi = 0x7fffffff;
#pragma unroll
                for (int j = 0; j < 4; j++) {
                    int idx = (&cs.x)[j];
                    const float* crow = CB + ((size_t)lvl * KCODES + idx) * DDIM + lane * 8;
                    float p = 0.f;
#pragma unroll
                    for (int u = 0; u < 8; u++) p = fmaf(rrow[u], crow[u], p);
#pragma unroll
                    for (int o = 16; o; o >>= 1) p += __shfl_xor_sync(0xffffffffu, p, o);
                    float dd = fmaf(-2.f, p, r2t + e2Sh[idx]);
                    if (dd < bd || (dd == bd && idx < bi)) { bd = dd; bi = idx; }
                }
                if (lane == 0) bestI[tok] = bi;
            }
        }
        __syncthreads();

        // ---- residual update + new r2 + commit (4 threads / token) -------
        {
            int t = tid >> 2, h = tid & 3;
            if (t < TMLOC) {
                int b = bestI[t];
                const float* qv = CB + ((size_t)lvl * KCODES + b) * DDIM + h * 64;
                float* rr = Rsh + t * RS + h * 64;
                double ss = 0.0;
                for (int k = 0; k < 64; k += 4) {
                    float4 q4 = *(const float4*)(qv + k);
                    float n0 = rr[k]     - q4.x;
                    float n1 = rr[k + 1] - q4.y;
                    float n2 = rr[k + 2] - q4.z;
                    float n3 = rr[k + 3] - q4.w;
                    rr[k] = n0; rr[k + 1] = n1; rr[k + 2] = n2; rr[k + 3] = n3;
                    ss += (double)n0 * n0 + (double)n1 * n1
                        + (double)n2 * n2 + (double)n3 * n3;
                }
                redD[tid] = ss;
                commitAcc += ss;
            }
            __syncthreads();
            if (t < TMLOC && !h)
                r2Sh[t] = (float)(redD[tid] + redD[tid + 1] + redD[tid + 2] + redD[tid + 3]);
        }
        __syncthreads();
    } // levels

    // ---- y = x - r_final ---------------------------------------------------
    for (int idx = tid; idx < TMLOC * (DDIM / 4); idx += THREADS) {
        int t = idx >> 6, dq = (idx & 63) << 2;
        float4 xv = *(const float4*)(Xblk + (long long)t * DDIM + dq);
        const float* rr = Rsh + t * RS + dq;
        float4 y;
        y.x = xv.x - rr[0]; y.y = xv.y - rr[1];
        y.z = xv.z - rr[2]; y.w = xv.w - rr[3];
        *(float4*)(Y + (tokenBase + t) * DDIM + dq) = y;
    }

    // ---- deterministic per-block commit partial ----------------------------
    redD[tid] = commitAcc;
    for (int s = THREADS / 2; s > 0; s >>= 1) {
        __syncthreads();
        if (tid < s) redD[tid] += redD[tid + s];
    }
    if (tid == 0) g_commitPartial[blockIdx.x] = redD[0];
}

// ---------------------------------------------------------------------------
__global__ __launch_bounds__(THREADS, 1)
void rvq_mma(const float* __restrict__ X, const float* __restrict__ CB,
             float* __restrict__ Y) {
    extern __shared__ char smem[];
    if (blockIdx.x < NBIG) {
        rvq_body<128>(X, CB, Y, smem, (long long)blockIdx.x * 128);
    } else {
        rvq_body<64>(X, CB, Y, smem,
                     (long long)NBIG * 128 + (long long)(blockIdx.x - NBIG) * 64);
    }
}

// ---------------------------------------------------------------------------
__global__ void finalize_kernel(float* __restrict__ Y, int out_size) {
    __shared__ double sd[1024];
    int tid = threadIdx.x;
    sd[tid] = (tid < GRID) ? g_commitPartial[tid] : 0.0;
    for (int s = 512; s > 0; s >>= 1) {
        __syncthreads();
        if (tid < s) sd[tid] += sd[tid + s];
    }
    if (tid == 0) {
        double mean = sd[0] / (double)((long long)NTOK * DDIM);
        float commit = (float)(0.25 * mean);
        long long numel = (long long)NTOK * DDIM;
        for (long long j = numel; j < (long long)out_size; j++) Y[j] = commit;
    }
}

extern "C" void kernel_launch(void* const* d_in, const int* in_sizes, int n_in,
                              void* d_out, int out_size) {
    const float* X  = (const float*)d_in[0];
    const float* CB = (const float*)d_in[1];
    float* Y = (float*)d_out;

    cudaFuncSetAttribute(rvq_mma, cudaFuncAttributeMaxDynamicSharedMemorySize,
                         SMEM_TOTAL);

    prep_all<<<512, 256>>>(CB);
    rvq_mma<<<GRID, THREADS, SMEM_TOTAL>>>(X, CB, Y);
    finalize_kernel<<<1, 1024>>>(Y, out_size);
}